// round 10
// baseline (speedup 1.0000x reference)
#include <cuda_runtime.h>

#define TT 128
#define BB 512
#define QQ 50
#define BQ (BB * QQ)                 // 25600
#define GAMMA_F 0.99f
#define NCH 8
#define CHL 16
#define RST 52                       // smem row stride, 16B aligned
#define NTHR_F 224                   // 7 warps; 16 units x 13 jt = 208 active

// Per-chunk affine composites per chain: rets[chunk_lo] = A*rets[chunk_hi+1] + B
__device__ float2 g_AB[NCH * BQ];

// ---------------------------------------------------------------------------
// Kernel 1: chunk composites (R4's measured-best form: plain loop, 128 thr).
// ---------------------------------------------------------------------------
__global__ __launch_bounds__(128)
void k_scan(const float* __restrict__ reward,
            const int*   __restrict__ step_type,
            const float* __restrict__ discount,
            const float* __restrict__ tvalue,
            float*       __restrict__ out)
{
    const int n = blockIdx.x * 128 + threadIdx.x;   // 0..25599 chain
    const int c = blockIdx.y;
    if (c == 0 && n < BB) out[(TT - 1) * BB + n] = 0.0f;   // poisoned last row
    const int b = n / QQ;
    const int lo = c * CHL;
    const int hi = (c == NCH - 1) ? (TT - 2) : (lo + CHL - 1);

    float A = 1.0f, Bv = 0.0f;
    #pragma unroll
    for (int k = 0; k < CHL; ++k) {
        const int t = hi - k;
        if (t >= lo) {
            float tv = tvalue[t * BQ + n];
            int   il = step_type[t * BB + b];
            float r  = reward[(t + 1) * BB + b];
            float d  = discount[(t + 1) * BB + b] * GAMMA_F;
            float a  = (il == 2) ? 0.0f : d;
            A  = a * A;
            Bv = fmaf(a, Bv, (il == 2) ? tv : r);
        }
    }
    g_AB[c * BQ + n] = make_float2(A, Bv);
}

// ---------------------------------------------------------------------------
// Kernel 2 (fused): block = (b, 16-t chunk). Seed from L2-hot composites,
// 16-step in-smem walk, then pairwise quantile-Huber with 4 j's per thread
// (each LDS.128 of returns feeds 16 PAIR2s -> smem no longer co-limiting).
// ---------------------------------------------------------------------------

#define PAIR2(r2_, nv2_, S2_, D2_) do {                                        \
    unsigned long long x2_, c2_, m2_, t2_;                                     \
    asm("add.rn.f32x2 %0, %1, %2;" : "=l"(x2_) : "l"(r2_), "l"(nv2_));         \
    float xl_, xh_;                                                            \
    asm("mov.b64 {%0, %1}, %2;" : "=f"(xl_), "=f"(xh_) : "l"(x2_));            \
    float ml_ = fminf(fabsf(xl_), 1.0f);                                       \
    float mh_ = fminf(fabsf(xh_), 1.0f);                                       \
    float cl_ = __int_as_float((__float_as_int(xl_) & 0x80000000) |            \
                               __float_as_int(ml_));                           \
    float ch_ = __int_as_float((__float_as_int(xh_) & 0x80000000) |            \
                               __float_as_int(mh_));                           \
    asm("mov.b64 %0, {%1, %2};" : "=l"(c2_) : "f"(cl_), "f"(ch_));             \
    asm("mov.b64 %0, {%1, %2};" : "=l"(m2_) : "f"(ml_), "f"(mh_));             \
    asm("fma.rn.f32x2 %0, %1, %2, %3;" : "=l"(t2_)                             \
        : "l"(c2_), "l"(MH2), "l"(x2_));                                       \
    asm("fma.rn.f32x2 %0, %1, %2, %0;" : "+l"(S2_) : "l"(c2_), "l"(t2_));      \
    asm("fma.rn.f32x2 %0, %1, %2, %0;" : "+l"(D2_) : "l"(m2_), "l"(t2_));      \
} while (0)

__global__ __launch_bounds__(NTHR_F, 5)
void k_cpair(const float* __restrict__ reward,
             const int*   __restrict__ step_type,
             const float* __restrict__ discount,
             const float* __restrict__ value,
             const float* __restrict__ tvalue,
             float*       __restrict__ out)
{
    __shared__ __align__(16) float s_ret[CHL][RST];
    __shared__ float s_part[CHL][QQ];
    __shared__ float s_a[CHL], s_r[CHL];
    __shared__ int   s_il[CHL];

    const int tid = threadIdx.x;
    const int b   = blockIdx.x;
    const int c   = blockIdx.y;                      // chunk 0..7
    const int lo  = c * CHL;
    const int hi  = (c == NCH - 1) ? (TT - 2) : (lo + CHL - 1);
    const int nu  = hi - lo + 1;                     // 16 (or 15 for c=7)

    // ---- Stage tvalue rows (float2) + per-t scalars ----
    const int nstage = nu * (QQ / 2);
    for (int idx = tid; idx < nstage; idx += NTHR_F) {
        const int u  = idx / (QQ / 2);
        const int q2 = idx - u * (QQ / 2);
        ((float2*)&s_ret[u][0])[q2] =
            *(const float2*)&tvalue[(lo + u) * BQ + b * QQ + 2 * q2];
    }
    if (tid < nu) {
        const int t = lo + tid;
        const int il = step_type[t * BB + b];
        s_il[tid] = il;
        s_r[tid]  = reward[(t + 1) * BB + b];
        s_a[tid]  = (il == 2) ? 0.0f
                              : discount[(t + 1) * BB + b] * GAMMA_F;
    }

    // ---- Seed (overlaps staging): compose L2-hot composites above chunk ----
    float carry = 0.0f;
    if (tid < QQ) {
        carry = tvalue[(TT - 1) * BQ + b * QQ + tid];        // rets[127]
        float2 ab[NCH];
        #pragma unroll
        for (int cc = NCH - 1; cc >= 1; --cc)                // independent loads
            if (cc > c) ab[cc] = g_AB[cc * BQ + b * QQ + tid];
        #pragma unroll
        for (int cc = NCH - 1; cc >= 1; --cc)
            if (cc > c) carry = fmaf(ab[cc].x, carry, ab[cc].y);
    }
    __syncthreads();

    // ---- 16-step in-smem walk with rolling prefetch ----
    if (tid < QQ) {
        int   k  = nu - 1;
        float tv = s_ret[k][tid];
        float aa = s_a[k];
        float rr = s_r[k];
        int   il = s_il[k];
        for (; k > 0; --k) {
            float tvn = s_ret[k - 1][tid];
            float aan = s_a[k - 1];
            float rrn = s_r[k - 1];
            int   iln = s_il[k - 1];
            carry = fmaf(aa, carry, (il == 2) ? tv : rr);
            s_ret[k][tid] = carry;
            tv = tvn; aa = aan; rr = rrn; il = iln;
        }
        carry = fmaf(aa, carry, (il == 2) ? tv : rr);
        s_ret[0][tid] = carry;
    }
    __syncthreads();

    // ---- Pairwise quantile-Huber: thread = (u, 4 j's) ----
    const int u  = tid / 13;
    const int jt = tid - u * 13;                     // j group: 4*jt .. 4*jt+3
    if (tid < CHL * 13 && u < nu) {
        const int vbase = (lo + u) * BQ + b * QQ + 4 * jt;
        const float2 va = *(const float2*)&value[vbase];      // j = 4jt, 4jt+1
        const float2 vb = *(const float2*)&value[vbase + 2];  // j = 4jt+2, +3
        unsigned long long nv2[4];
        {
            float n0 = -va.x, n1 = -va.y, n2 = -vb.x, n3 = -vb.y;
            asm("mov.b64 %0, {%1, %1};" : "=l"(nv2[0]) : "f"(n0));
            asm("mov.b64 %0, {%1, %1};" : "=l"(nv2[1]) : "f"(n1));
            asm("mov.b64 %0, {%1, %1};" : "=l"(nv2[2]) : "f"(n2));
            asm("mov.b64 %0, {%1, %1};" : "=l"(nv2[3]) : "f"(n3));
        }
        const unsigned long long MH2 = 0xBF000000BF000000ULL;   // (-0.5,-0.5)
        unsigned long long S2[4] = {0, 0, 0, 0};
        unsigned long long D2[4] = {0, 0, 0, 0};

        const ulonglong2* rp2 = (const ulonglong2*)&s_ret[u][0];
        #pragma unroll
        for (int p = 0; p < 12; ++p) {               // 48 returns via LDS.128
            ulonglong2 rr = rp2[p];
            #pragma unroll
            for (int jg = 0; jg < 4; ++jg) PAIR2(rr.x, nv2[jg], S2[jg], D2[jg]);
            #pragma unroll
            for (int jg = 0; jg < 4; ++jg) PAIR2(rr.y, nv2[jg], S2[jg], D2[jg]);
        }
        {                                            // returns 48, 49
            unsigned long long rt_ = *(const unsigned long long*)&s_ret[u][48];
            #pragma unroll
            for (int jg = 0; jg < 4; ++jg) PAIR2(rt_, nv2[jg], S2[jg], D2[jg]);
        }

        #pragma unroll
        for (int jg = 0; jg < 4; ++jg) {
            const int j = 4 * jt + jg;
            if (j < QQ) {                            // jt=12 only stores j=48,49
                float sl, sh, dl, dh;
                asm("mov.b64 {%0, %1}, %2;" : "=f"(sl), "=f"(sh) : "l"(S2[jg]));
                asm("mov.b64 {%0, %1}, %2;" : "=f"(dl), "=f"(dh) : "l"(D2[jg]));
                const float tau = ((float)j + 0.5f) * (1.0f / QQ);
                s_part[u][j] = fmaf(tau - 0.5f, dl + dh, 0.5f * (sl + sh));
            }
        }
    }
    __syncthreads();

    // ---- Deterministic fixed-order j-reduction ----
    if (tid < nu) {
        float s = 0.0f;
        #pragma unroll
        for (int j = 0; j < QQ; ++j) s += s_part[tid][j];
        out[(lo + tid) * BB + b] = s * (1.0f / QQ);
    }
}

extern "C" void kernel_launch(void* const* d_in, const int* in_sizes, int n_in,
                              void* d_out, int out_size)
{
    const float* reward    = (const float*)d_in[0];
    const int*   step_type = (const int*)  d_in[1];
    const float* discount  = (const float*)d_in[2];
    const float* value     = (const float*)d_in[3];
    const float* tvalue    = (const float*)d_in[4];
    float*       out       = (float*)d_out;

    dim3 gs(BQ / 128, NCH);                          // (200, 8)
    k_scan<<<gs, 128>>>(reward, step_type, discount, tvalue, out);

    dim3 gf(BB, NCH);                                // 4096 blocks
    k_cpair<<<gf, NTHR_F>>>(reward, step_type, discount, value, tvalue, out);
}

// round 11
// speedup vs baseline: 1.0491x; 1.0491x over previous
#include <cuda_runtime.h>

#define TT 128
#define BB 512
#define QQ 50
#define BQ (BB * QQ)                 // 25600
#define NUNITS ((TT - 1) * BB)       // 65024
#define GAMMA_F 0.99f
#define UNITS 10                     // units per k_pairs block (10*25 = 250 thr)
#define RST 52                       // smem row stride, 16B aligned

// Discounted returns, row gu = t*BB+b at [gu*QQ .. gu*QQ+49].
__device__ float g_ret[(TT - 1) * BQ];

// ---------------------------------------------------------------------------
// Kernel 1: full backward recurrence, one block per b. Stage all 128 tvalue
// rows into smem (coalesced), 50 threads walk 127 steps with rolling
// prefetch (4-cyc fma chain), streaming g_ret stores.
// ---------------------------------------------------------------------------
__global__ __launch_bounds__(256)
void k_ret(const float* __restrict__ reward,
           const int*   __restrict__ step_type,
           const float* __restrict__ discount,
           const float* __restrict__ tvalue,
           float*       __restrict__ out)
{
    __shared__ __align__(16) float s_tv[TT][RST];
    __shared__ float s_a[TT], s_r[TT];
    __shared__ int   s_il[TT];

    const int tid = threadIdx.x;
    const int b   = blockIdx.x;

    // Stage 128 rows of tvalue[:, b, :] (float2, rows gmem-contiguous 200B)
    for (int idx = tid; idx < TT * (QQ / 2); idx += 256) {
        const int t  = idx / (QQ / 2);
        const int q2 = idx - t * (QQ / 2);
        ((float2*)&s_tv[t][0])[q2] =
            *(const float2*)&tvalue[t * BQ + b * QQ + 2 * q2];
    }
    // Per-t scalars for t = 0..126
    if (tid < TT - 1) {
        const int il = step_type[tid * BB + b];
        s_il[tid] = il;
        s_r[tid]  = reward[(tid + 1) * BB + b];
        s_a[tid]  = (il == 2) ? 0.0f
                              : discount[(tid + 1) * BB + b] * GAMMA_F;
    }
    if (tid == 0) out[(TT - 1) * BB + b] = 0.0f;     // poisoned last row
    __syncthreads();

    // Walk t = 126 .. 0, rolling prefetch; stream stores to g_ret.
    if (tid < QQ) {
        float carry = s_tv[TT - 1][tid];             // rets[127]
        int   k  = TT - 2;
        float tv = s_tv[k][tid];
        float aa = s_a[k];
        float rr = s_r[k];
        int   il = s_il[k];
        for (; k > 0; --k) {
            float tvn = s_tv[k - 1][tid];
            float aan = s_a[k - 1];
            float rrn = s_r[k - 1];
            int   iln = s_il[k - 1];
            carry = fmaf(aa, carry, (il == 2) ? tv : rr);
            g_ret[k * BQ + b * QQ + tid] = carry;
            tv = tvn; aa = aan; rr = rrn; il = iln;
        }
        carry = fmaf(aa, carry, (il == 2) ? tv : rr);
        g_ret[b * QQ + tid] = carry;                 // t = 0
    }
}

// ---------------------------------------------------------------------------
// Kernel 2: pairwise quantile-Huber (R8 form — measured at structural floor).
//   x = ret_i - v_j;  m = min(|x|,1);  c = (x&sign)|m;  t = x - 0.5c
//   h = c*t, sgn(x)*h = m*t ;  loss_j = 0.5*S + (tau_j-0.5)*D
// ---------------------------------------------------------------------------

#define PAIR2(r2_, nv2_, S2_, D2_) do {                                        \
    unsigned long long x2_, c2_, m2_, t2_;                                     \
    asm("add.rn.f32x2 %0, %1, %2;" : "=l"(x2_) : "l"(r2_), "l"(nv2_));         \
    float xl_, xh_;                                                            \
    asm("mov.b64 {%0, %1}, %2;" : "=f"(xl_), "=f"(xh_) : "l"(x2_));            \
    float ml_ = fminf(fabsf(xl_), 1.0f);                                       \
    float mh_ = fminf(fabsf(xh_), 1.0f);                                       \
    float cl_ = __int_as_float((__float_as_int(xl_) & 0x80000000) |            \
                               __float_as_int(ml_));                           \
    float ch_ = __int_as_float((__float_as_int(xh_) & 0x80000000) |            \
                               __float_as_int(mh_));                           \
    asm("mov.b64 %0, {%1, %2};" : "=l"(c2_) : "f"(cl_), "f"(ch_));             \
    asm("mov.b64 %0, {%1, %2};" : "=l"(m2_) : "f"(ml_), "f"(mh_));             \
    asm("fma.rn.f32x2 %0, %1, %2, %3;" : "=l"(t2_)                             \
        : "l"(c2_), "l"(MH2), "l"(x2_));                                       \
    asm("fma.rn.f32x2 %0, %1, %2, %0;" : "+l"(S2_) : "l"(c2_), "l"(t2_));      \
    asm("fma.rn.f32x2 %0, %1, %2, %0;" : "+l"(D2_) : "l"(m2_), "l"(t2_));      \
} while (0)

__global__ __launch_bounds__(256)
void k_pairs(const float* __restrict__ value,
             float*       __restrict__ out)
{
    __shared__ __align__(16) float s_ret[UNITS][RST];
    __shared__ float s_part[UNITS][QQ];

    const int tid = threadIdx.x;
    const int gu0 = blockIdx.x * UNITS;
    const int nu  = min(UNITS, NUNITS - gu0);

    const int u  = tid / 25;
    const int jp = tid - u * 25;

    // Stage: 250 float2 loads (rows gu0..gu0+nu-1 are gmem-contiguous).
    if (tid < UNITS * 25 && u < nu)
        ((float2*)&s_ret[u][0])[jp] =
            *(const float2*)&g_ret[gu0 * QQ + 2 * tid];
    __syncthreads();

    if (tid < UNITS * 25 && u < nu) {
        const int gu = gu0 + u;
        const float2 v2 = *(const float2*)&value[gu * QQ + 2 * jp];
        unsigned long long nv2a, nv2b;
        {
            float na = -v2.x, nb = -v2.y;
            asm("mov.b64 %0, {%1, %1};" : "=l"(nv2a) : "f"(na));
            asm("mov.b64 %0, {%1, %1};" : "=l"(nv2b) : "f"(nb));
        }
        const unsigned long long MH2 = 0xBF000000BF000000ULL;   // (-0.5,-0.5)
        unsigned long long S2a = 0, D2a = 0, S2b = 0, D2b = 0;

        const ulonglong2* rp2 = (const ulonglong2*)&s_ret[u][0];
        #pragma unroll
        for (int p = 0; p < 12; ++p) {               // 48 returns via LDS.128
            ulonglong2 rr = rp2[p];
            PAIR2(rr.x, nv2a, S2a, D2a);
            PAIR2(rr.x, nv2b, S2b, D2b);
            PAIR2(rr.y, nv2a, S2a, D2a);
            PAIR2(rr.y, nv2b, S2b, D2b);
        }
        {                                            // returns 48, 49
            unsigned long long rt_ = *(const unsigned long long*)&s_ret[u][48];
            PAIR2(rt_, nv2a, S2a, D2a);
            PAIR2(rt_, nv2b, S2b, D2b);
        }

        float sl, sh, dl, dh;
        asm("mov.b64 {%0, %1}, %2;" : "=f"(sl), "=f"(sh) : "l"(S2a));
        asm("mov.b64 {%0, %1}, %2;" : "=f"(dl), "=f"(dh) : "l"(D2a));
        const float taua = (2 * jp + 0.5f) * (1.0f / QQ);
        s_part[u][2 * jp]     = fmaf(taua - 0.5f, dl + dh, 0.5f * (sl + sh));

        asm("mov.b64 {%0, %1}, %2;" : "=f"(sl), "=f"(sh) : "l"(S2b));
        asm("mov.b64 {%0, %1}, %2;" : "=f"(dl), "=f"(dh) : "l"(D2b));
        const float taub = (2 * jp + 1.5f) * (1.0f / QQ);
        s_part[u][2 * jp + 1] = fmaf(taub - 0.5f, dl + dh, 0.5f * (sl + sh));
    }
    __syncthreads();

    // Deterministic fixed-order j-reduction, one thread per unit.
    if (tid < nu) {
        float s = 0.0f;
        #pragma unroll
        for (int j = 0; j < QQ; ++j) s += s_part[tid][j];
        out[gu0 + tid] = s * (1.0f / QQ);            // out idx t*BB+b == gu
    }
}

extern "C" void kernel_launch(void* const* d_in, const int* in_sizes, int n_in,
                              void* d_out, int out_size)
{
    const float* reward    = (const float*)d_in[0];
    const int*   step_type = (const int*)  d_in[1];
    const float* discount  = (const float*)d_in[2];
    const float* value     = (const float*)d_in[3];
    const float* tvalue    = (const float*)d_in[4];
    float*       out       = (float*)d_out;

    k_ret<<<BB, 256>>>(reward, step_type, discount, tvalue, out);

    const int nblocks = (NUNITS + UNITS - 1) / UNITS;   // 6503
    k_pairs<<<nblocks, 256>>>(value, out);
}